// round 15
// baseline (speedup 1.0000x reference)
#include <cuda_runtime.h>
#include <cstdint>

// Covariance pooling: y[b] = (1/M) X Xᵀ - μ μᵀ, X = x[b] as [C=128, M=4096].
// tf32 mma.sync SYRK combining R11's symmetry (3 of 4 64x64 tiles) with R13's
// occupancy-2 structure. Balanced warp jobs: each of 4 warps owns
//   - one DIAG half-tile (32x64) for all 4 k8-steps  (64 MMA/k-tile)
//   - one OFF half-tile (32x64) for 2 k8-steps        (32 MMA/k-tile)
// = 96 MMA/SMSP/k-tile (0.75x R13) with 128 acc regs (fits occ 2).
// Kernel 1 (partial): 256 CTAs = 64 batches x 4 K-quarters; 128 threads;
//   cp.async 3-stage pipeline; raw-fp32 into tf32 MMA (debias CORR); exact
//   fp32 row sums in-pipeline; off halves combined via SMEM.
// Kernel 2 (finish): 512 CTAs; combines 4 K-quarters, mean subtraction,
//   mirrors the off-diagonal tile into the lower triangle.

#define DINLINE __device__ __forceinline__

static constexpr int Bn = 64;
static constexpr int Cn = 128;
static constexpr int Mn = 4096;
static constexpr int KSPLIT = 4;
static constexpr int KQ = Mn / KSPLIT;     // 1024
static constexpr int KT = 32;              // k floats per tile
static constexpr int NKT = KQ / KT;        // 32 tiles
static constexpr int PADB = 144;           // bytes per SMEM row (36 floats)
static constexpr int STAGES = 3;
static constexpr int STAGE_B = Cn * PADB;  // 18432
static constexpr int SMEM_B = STAGES * STAGE_B;  // 55296 -> 2 CTAs/SM

// tf32 truncation debias: 1/(1 - 2 * 2^-11 * (1/(2 ln 2)))
static constexpr float CORR = 1.00070466f;

__device__ float g_part[KSPLIT * Bn][3][64 * 64];  // [cta][0=d00,1=d11,2=off01]
__device__ float g_sums[KSPLIT * Bn][Cn];

DINLINE void mma_tf32(float d[4], const uint32_t a[4], uint32_t b0, uint32_t b1) {
    asm volatile(
        "mma.sync.aligned.m16n8k8.row.col.f32.tf32.tf32.f32 "
        "{%0,%1,%2,%3}, {%4,%5,%6,%7}, {%8,%9}, {%0,%1,%2,%3};"
        : "+f"(d[0]), "+f"(d[1]), "+f"(d[2]), "+f"(d[3])
        : "r"(a[0]), "r"(a[1]), "r"(a[2]), "r"(a[3]), "r"(b0), "r"(b1));
}
DINLINE void ldsm_x4(uint32_t r[4], uint32_t addr) {
    asm volatile("ldmatrix.sync.aligned.m8n8.x4.shared.b16 {%0,%1,%2,%3}, [%4];"
                 : "=r"(r[0]), "=r"(r[1]), "=r"(r[2]), "=r"(r[3]) : "r"(addr));
}
DINLINE uint32_t smem_u32(const void* p) {
    uint32_t a;
    asm("{ .reg .u64 t; cvta.to.shared.u64 t, %1; cvt.u32.u64 %0, t; }"
        : "=r"(a) : "l"(p));
    return a;
}
DINLINE void cp16(uint32_t dst, const void* src) {
    asm volatile("cp.async.cg.shared.global [%0], [%1], 16;"
                 :: "r"(dst), "l"(src) : "memory");
}
DINLINE void cp_commit() { asm volatile("cp.async.commit_group;" ::: "memory"); }
template <int N> DINLINE void cp_wait() {
    asm volatile("cp.async.wait_group %0;" :: "n"(N) : "memory");
}

__global__ __launch_bounds__(128, 2)
void covpool_partial(const float* __restrict__ x) {
    extern __shared__ char smem[];
    const uint32_t sb = smem_u32(smem);

    const int t    = threadIdx.x;
    const int warp = t >> 5;
    const int lane = t & 31;
    const int cta  = blockIdx.x;        // 0..255
    const int s    = cta & 3;           // K-quarter
    const int b    = cta >> 2;

    // loader: one row per thread, 128 B per k-tile
    const float* xrow = x + (size_t)b * Cn * Mn + (size_t)t * Mn + (size_t)s * KQ;
    const uint32_t ldst = (uint32_t)(t * PADB);

    // ---- warp jobs ----
    // diag half: A rows [dwm, dwm+32), B rows (=cols) [dwn, dwn+64), k8 0..3
    const int dwm = (warp >> 1) * 64 + (warp & 1) * 32;
    const int dwn = (warp >> 1) * 64;
    // off half: A rows [owm, owm+32), B rows 64..127, k8 {oks, oks+1}
    const int owm = (warp >> 1) * 32;
    const int oks = (warp & 1) * 2;

    const uint32_t aoffD = (uint32_t)((dwm + (lane & 15)) * PADB + (lane >> 4) * 16);
    const uint32_t boffD = (uint32_t)((dwn + (lane & 7) + ((lane >> 4) * 8)) * PADB
                                      + ((lane >> 3) & 1) * 16);
    const uint32_t aoffO = (uint32_t)((owm + (lane & 15)) * PADB + (lane >> 4) * 16);
    const uint32_t boffO = (uint32_t)((64 + (lane & 7) + ((lane >> 4) * 8)) * PADB
                                      + ((lane >> 3) & 1) * 16);
    const int g  = lane >> 2;
    const int tg = lane & 3;

    float accD[2][8][4], accO[2][8][4];
#pragma unroll
    for (int mi = 0; mi < 2; mi++)
#pragma unroll
        for (int ni = 0; ni < 8; ni++)
#pragma unroll
            for (int j = 0; j < 4; j++) { accD[mi][ni][j] = 0.0f; accO[mi][ni][j] = 0.0f; }

    float rowsum = 0.0f;

    // prologue: stages 0,1
#pragma unroll
    for (int p = 0; p < STAGES - 1; p++) {
        const uint32_t d0 = sb + p * STAGE_B + ldst;
        const float* src = xrow + p * KT;
#pragma unroll
        for (int i = 0; i < 8; i++) cp16(d0 + i * 16, src + i * 4);
        cp_commit();
    }

    int cur = 0, iss = STAGES - 1;
    for (int kt = 0; kt < NKT; kt++) {
        cp_wait<STAGES - 2>();
        __syncthreads();
        if (kt + STAGES - 1 < NKT) {
            const uint32_t d0 = sb + iss * STAGE_B + ldst;
            const float* src = xrow + (kt + STAGES - 1) * KT;
#pragma unroll
            for (int i = 0; i < 8; i++) cp16(d0 + i * 16, src + i * 4);
        }
        cp_commit();

        const uint32_t base = sb + cur * STAGE_B;

        // exact fp32 row sum of this thread's own row
#pragma unroll
        for (int i = 0; i < 8; i++) {
            float4 v = *(const float4*)(smem + cur * STAGE_B + t * PADB + i * 16);
            rowsum += v.x + v.y + v.z + v.w;
        }

        // ---- diag half: 4 k8-steps, 16 MMA each ----
#pragma unroll
        for (int ks = 0; ks < 4; ks++) {
            const uint32_t k0 = (uint32_t)(ks * 32);
            uint32_t A[2][4], Bf[4][4];
#pragma unroll
            for (int mi = 0; mi < 2; mi++)
                ldsm_x4(A[mi], base + aoffD + mi * 16 * PADB + k0);
#pragma unroll
            for (int jn = 0; jn < 4; jn++)
                ldsm_x4(Bf[jn], base + boffD + jn * 16 * PADB + k0);
#pragma unroll
            for (int mi = 0; mi < 2; mi++)
#pragma unroll
                for (int jn = 0; jn < 4; jn++) {
                    mma_tf32(accD[mi][2 * jn],     A[mi], Bf[jn][0], Bf[jn][1]);
                    mma_tf32(accD[mi][2 * jn + 1], A[mi], Bf[jn][2], Bf[jn][3]);
                }
        }
        // ---- off half: 2 k8-steps, 16 MMA each ----
#pragma unroll
        for (int ksi = 0; ksi < 2; ksi++) {
            const uint32_t k0 = (uint32_t)((oks + ksi) * 32);
            uint32_t A[2][4], Bf[4][4];
#pragma unroll
            for (int mi = 0; mi < 2; mi++)
                ldsm_x4(A[mi], base + aoffO + mi * 16 * PADB + k0);
#pragma unroll
            for (int jn = 0; jn < 4; jn++)
                ldsm_x4(Bf[jn], base + boffO + jn * 16 * PADB + k0);
#pragma unroll
            for (int mi = 0; mi < 2; mi++)
#pragma unroll
                for (int jn = 0; jn < 4; jn++) {
                    mma_tf32(accO[mi][2 * jn],     A[mi], Bf[jn][0], Bf[jn][1]);
                    mma_tf32(accO[mi][2 * jn + 1], A[mi], Bf[jn][2], Bf[jn][3]);
                }
        }

        cur = (cur + 1 == STAGES) ? 0 : cur + 1;
        iss = (iss + 1 == STAGES) ? 0 : iss + 1;
    }

    g_sums[cta][t] = rowsum;

    // ---- diag halves: store directly ----
    {
        float* gp = g_part[cta][warp >> 1];
#pragma unroll
        for (int mi = 0; mi < 2; mi++) {
            const int lr = (warp & 1) * 32 + mi * 16 + g;   // local row in 64x64
#pragma unroll
            for (int ni = 0; ni < 8; ni++) {
                const int c0 = ni * 8 + 2 * tg;
                *(float2*)(gp + lr * 64 + c0) =
                    make_float2(accD[mi][ni][0], accD[mi][ni][1]);
                *(float2*)(gp + (lr + 8) * 64 + c0) =
                    make_float2(accD[mi][ni][2], accD[mi][ni][3]);
            }
        }
    }

    // ---- off halves: combine k-split pairs (w1->w0 offa, w3->w2 offb) ----
    cp_wait<0>();
    __syncthreads();
    if (warp & 1) {                 // w1, w3 dump
        float4* d = (float4*)(smem + (warp >> 1) * 8192) + lane * 16;
#pragma unroll
        for (int mi = 0; mi < 2; mi++)
#pragma unroll
            for (int ni = 0; ni < 8; ni++)
                d[mi * 8 + ni] = make_float4(accO[mi][ni][0], accO[mi][ni][1],
                                             accO[mi][ni][2], accO[mi][ni][3]);
    }
    __syncthreads();
    if ((warp & 1) == 0) {          // w0, w2 reduce + store
        const float4* sp = (const float4*)(smem + (warp >> 1) * 8192) + lane * 16;
        float* gp = g_part[cta][2];
#pragma unroll
        for (int mi = 0; mi < 2; mi++) {
            const int lr = owm + mi * 16 + g;               // local row in 64x64
#pragma unroll
            for (int ni = 0; ni < 8; ni++) {
                float4 v = sp[mi * 8 + ni];
                const int c0 = ni * 8 + 2 * tg;
                *(float2*)(gp + lr * 64 + c0) =
                    make_float2(accO[mi][ni][0] + v.x, accO[mi][ni][1] + v.y);
                *(float2*)(gp + (lr + 8) * 64 + c0) =
                    make_float2(accO[mi][ni][2] + v.z, accO[mi][ni][3] + v.w);
            }
        }
    }
}

__global__ __launch_bounds__(256, 2)
void covpool_finish(float* __restrict__ y) {
    __shared__ float mu[Cn];
    const int t    = threadIdx.x;
    const int b    = blockIdx.x >> 3;
    const int sub  = blockIdx.x & 7;
    const int q    = sub >> 1;
    const int half = sub & 1;
    if (t < Cn)
        mu[t] = (g_sums[4 * b][t] + g_sums[4 * b + 1][t]
               + g_sums[4 * b + 2][t] + g_sums[4 * b + 3][t]) * (1.0f / (float)Mn);
    __syncthreads();

    const float a = CORR * (1.0f / (float)Mn);
    float* yb = y + (size_t)b * Cn * Cn;

    if (q == 0 || q == 3) {                 // diagonal quadrants
        const int d  = (q == 0) ? 0 : 64;
        const int ti = (q == 0) ? 0 : 1;
        const float4* G0 = (const float4*)g_part[4 * b][ti];
        const float4* G1 = (const float4*)g_part[4 * b + 1][ti];
        const float4* G2 = (const float4*)g_part[4 * b + 2][ti];
        const float4* G3 = (const float4*)g_part[4 * b + 3][ti];
#pragma unroll
        for (int k = 0; k < 2; k++) {
            const int e4 = t + (half * 2 + k) * 256;   // float4 idx in [0,1024)
            const int i  = e4 >> 4;
            const int j4 = e4 & 15;
            const float mr = mu[d + i];
            const float4 m = ((const float4*)mu)[(d >> 2) + j4];
            float4 p0 = G0[e4], p1 = G1[e4], p2 = G2[e4], p3 = G3[e4];
            float4 o;
            o.x = ((p0.x + p1.x) + (p2.x + p3.x)) * a - mr * m.x;
            o.y = ((p0.y + p1.y) + (p2.y + p3.y)) * a - mr * m.y;
            o.z = ((p0.z + p1.z) + (p2.z + p3.z)) * a - mr * m.z;
            o.w = ((p0.w + p1.w) + (p2.w + p3.w)) * a - mr * m.w;
            ((float4*)(yb + (size_t)(d + i) * Cn + d))[j4] = o;
        }
    } else if (q == 1) {                    // upper-right: rows 0-63, cols 64-127
        const float4* G0 = (const float4*)g_part[4 * b][2];
        const float4* G1 = (const float4*)g_part[4 * b + 1][2];
        const float4* G2 = (const float4*)g_part[4 * b + 2][2];
        const float4* G3 = (const float4*)g_part[4 * b + 3][2];
#pragma unroll
        for (int k = 0; k < 2; k++) {
            const int e4 = t + (half * 2 + k) * 256;
            const int i  = e4 >> 4;
            const int j4 = e4 & 15;
            const float mr = mu[i];
            const float4 m = ((const float4*)mu)[16 + j4];
            float4 p0 = G0[e4], p1 = G1[e4], p2 = G2[e4], p3 = G3[e4];
            float4 o;
            o.x = ((p0.x + p1.x) + (p2.x + p3.x)) * a - mr * m.x;
            o.y = ((p0.y + p1.y) + (p2.y + p3.y)) * a - mr * m.y;
            o.z = ((p0.z + p1.z) + (p2.z + p3.z)) * a - mr * m.z;
            o.w = ((p0.w + p1.w) + (p2.w + p3.w)) * a - mr * m.w;
            ((float4*)(yb + (size_t)i * Cn + 64))[j4] = o;
        }
    } else {                                // lower-left: transposed off tile
        const float* Ga = g_part[4 * b][2];
        const float* Gb = g_part[4 * b + 1][2];
        const float* Gc = g_part[4 * b + 2][2];
        const float* Gd = g_part[4 * b + 3][2];
#pragma unroll
        for (int k = 0; k < 2; k++) {
            const int e4 = t + (half * 2 + k) * 256;
            const int jj = e4 >> 4;          // out row 64+jj
            const int i0 = (e4 & 15) * 4;    // out cols i0..i0+3
            const float mr = mu[64 + jj];
            float4 o;
            o.x = (Ga[(i0 + 0) * 64 + jj] + Gb[(i0 + 0) * 64 + jj]
                 + Gc[(i0 + 0) * 64 + jj] + Gd[(i0 + 0) * 64 + jj]) * a - mr * mu[i0 + 0];
            o.y = (Ga[(i0 + 1) * 64 + jj] + Gb[(i0 + 1) * 64 + jj]
                 + Gc[(i0 + 1) * 64 + jj] + Gd[(i0 + 1) * 64 + jj]) * a - mr * mu[i0 + 1];
            o.z = (Ga[(i0 + 2) * 64 + jj] + Gb[(i0 + 2) * 64 + jj]
                 + Gc[(i0 + 2) * 64 + jj] + Gd[(i0 + 2) * 64 + jj]) * a - mr * mu[i0 + 2];
            o.w = (Ga[(i0 + 3) * 64 + jj] + Gb[(i0 + 3) * 64 + jj]
                 + Gc[(i0 + 3) * 64 + jj] + Gd[(i0 + 3) * 64 + jj]) * a - mr * mu[i0 + 3];
            *(float4*)(yb + (size_t)(64 + jj) * Cn + i0) = o;
        }
    }
}

extern "C" void kernel_launch(void* const* d_in, const int* in_sizes, int n_in,
                              void* d_out, int out_size) {
    (void)in_sizes; (void)n_in; (void)out_size;
    const float* x = (const float*)d_in[0];
    float* y = (float*)d_out;
    cudaFuncSetAttribute(covpool_partial,
                         cudaFuncAttributeMaxDynamicSharedMemorySize, SMEM_B);
    covpool_partial<<<KSPLIT * Bn, 128, SMEM_B>>>(x);
    covpool_finish<<<8 * Bn, 256>>>(y);
}